// round 7
// baseline (speedup 1.0000x reference)
#include <cuda_runtime.h>
#include <mma.h>
#include <math.h>

using namespace nvcuda;

#define NA 5000
#define NE 250000
#define FF 256
#define F3 768
#define NBF 20
#define LL 3
#define PIF 3.14159265358979323846f
#define CUTF 5.0f

// ---------------- scratch (device globals; no allocation allowed) -------------
__device__ float g_ns[2][NA * FF];
__device__ float g_nv[2][NA * 3 * FF];
__device__ float g_so[NA * F3];        // scalar_out / mlp_out (reused)
__device__ float g_hidden[NA * FF];    // MLP hidden
__device__ float g_cat[NA * 2 * FF];   // [Vn | node_scalar]
__device__ float g_Uv[NA * 3 * FF];
__device__ float g_Vv[NA * 3 * FF];
__device__ float g_sdat[NE * 24];      // CSR-sorted per edge: fcut,u0,u1,u2,rbf[20]
__device__ int   g_ssend[NE];          // CSR-sorted send index
__device__ int   g_counts[NA];
__device__ int   g_offsets[NA + 1];
__device__ int   g_cursor[NA];

// ---------------- small utility kernels --------------------------------------

__global__ void zero_csr_kernel(float* __restrict__ out,
                                const float* __restrict__ b2) {
    int i = blockIdx.x * blockDim.x + threadIdx.x;
    if (i < NA) { g_counts[i] = 0; g_cursor[i] = 0; out[i] = b2[0]; }
}

__global__ void init_nodes_kernel(const int* __restrict__ Z,
                                  const float* __restrict__ embed) {
    int a = blockIdx.x;
    int f = threadIdx.x;
    g_ns[0][a * FF + f] = embed[Z[a] * FF + f];
    g_nv[0][a * 3 * FF + 0 * FF + f] = 0.f;
    g_nv[0][a * 3 * FF + 1 * FF + f] = 0.f;
    g_nv[0][a * 3 * FF + 2 * FF + f] = 0.f;
}

__global__ void hist_kernel(const int* __restrict__ edge) {
    int e = blockIdx.x * blockDim.x + threadIdx.x;
    if (e >= NE) return;
    atomicAdd(&g_counts[edge[e * 2 + 0]], 1);
}

// exclusive scan of g_counts (NA=5000) -> g_offsets, single block of 1024
__global__ void scan_kernel() {
    __shared__ int ssum[1024];
    const int CH = 5;  // 1024*5 >= 5000
    int t = threadIdx.x;
    int base = t * CH;
    int local[CH];
    int sum = 0;
#pragma unroll
    for (int i = 0; i < CH; i++) {
        int idx = base + i;
        int v = (idx < NA) ? g_counts[idx] : 0;
        local[i] = sum;
        sum += v;
    }
    ssum[t] = sum;
    __syncthreads();
    for (int off = 1; off < 1024; off <<= 1) {
        int v = (t >= off) ? ssum[t - off] : 0;
        __syncthreads();
        ssum[t] += v;
        __syncthreads();
    }
    int pre = (t > 0) ? ssum[t - 1] : 0;
#pragma unroll
    for (int i = 0; i < CH; i++) {
        int idx = base + i;
        if (idx < NA) g_offsets[idx] = pre + local[i];
    }
    if (t == 1023) g_offsets[NA] = ssum[1023];
}

// per-edge precompute (rbf/fcut/unit) written DIRECTLY to CSR-sorted slot
__global__ void prep_scatter_kernel(const int* __restrict__ edge,
                                    const float* __restrict__ edge_diff,
                                    const float* __restrict__ edge_dist) {
    int e = blockIdx.x * blockDim.x + threadIdx.x;
    if (e >= NE) return;
    int r = edge[e * 2 + 0];
    int s = edge[e * 2 + 1];
    int pos = atomicAdd(&g_cursor[r], 1);
    int o = g_offsets[r] + pos;
    g_ssend[o] = s;
    float d = edge_dist[e];
    float inv = 1.f / d;
    float fcut = (d < CUTF) ? 0.5f * (cosf(PIF * d / CUTF) + 1.f) : 0.f;
    float* ed = g_sdat + (long)o * 24;
    ed[0] = fcut;
    ed[1] = edge_diff[e * 3 + 0] * inv;
    ed[2] = edge_diff[e * 3 + 1] * inv;
    ed[3] = edge_diff[e * 3 + 2] * inv;
#pragma unroll
    for (int n = 0; n < NBF; n++) {
        ed[4 + n] = sinf(d * (float)(n + 1) * (PIF / CUTF)) * inv;
    }
}

// ------------- 3xTF32 tensor-core GEMM: C = act(A @ B + bias) -----------------
// 64x64 tile, 128 threads (4 warps 2x2), warp 32x32 via 2x2 wmma 16x16x8.
// Double-buffered smem + DOUBLE register staging (prefetch distance 2).
// act: 0=none, 1=silu, 2=silu then dot with w2 -> atomicAdd into outp (readout).
// Dual mode (grid.z==2): block.z==1 uses B2/bias2/C2 (same A).
// K mult of 16, N mult of 64; M guarded.

#define STG 4352                    // floats per stage
#define AH_OFF 0                    // 64 x 17 (16 used)
#define AL_OFF 1088
#define BH_OFF 2176                 // 16 x 68 (64 used)
#define BL_OFF 3264

__global__ void __launch_bounds__(128)
tf32gemm_kernel(const float* __restrict__ A,
                const float* __restrict__ B,
                const float* __restrict__ bias,
                float* __restrict__ C,
                const float* __restrict__ B2,   // dual: second weights | act2: w2
                const float* __restrict__ bias2,
                float* __restrict__ C2,         // dual: second output | act2: out
                int M, int K, int N, int act) {
    __shared__ float sbuf[2 * STG];

    const float* w2g = B2;          // act==2 aliases
    float* outp = C2;
    if (blockIdx.z == 1) { B = B2; bias = bias2; C = C2; }

    const int tid = threadIdx.x;
    const int warp = tid >> 5;
    const int wr = warp >> 1;
    const int wc = warp & 1;
    const int row0 = blockIdx.y * 64;
    const int col0 = blockIdx.x * 64;

    const int ar = tid >> 1;              // A row 0..63
    const int ac8 = (tid & 1) * 8;        // 8-float half-row
    const int br = tid >> 4;              // B row 0..7 (+8 second)
    const int bc4 = (tid & 15) * 4;

    wmma::fragment<wmma::accumulator, 16, 16, 8, float> acc[2][2];
#pragma unroll
    for (int i = 0; i < 2; i++)
#pragma unroll
        for (int j = 0; j < 2; j++) wmma::fill_fragment(acc[i][j], 0.0f);

    const int nsteps = K >> 4;
    float4 st[2][4];                      // two staging sets

    auto load_tile = [&](int k0, int s) {
        int gr = row0 + ar;
        if (gr < M) {
            const float* ap = A + (long)gr * K + k0 + ac8;
            st[s][0] = *(const float4*)(ap);
            st[s][1] = *(const float4*)(ap + 4);
        } else {
            st[s][0] = make_float4(0.f, 0.f, 0.f, 0.f);
            st[s][1] = st[s][0];
        }
        const float* bp = B + (long)(k0 + br) * N + col0 + bc4;
        st[s][2] = *(const float4*)(bp);
        st[s][3] = *(const float4*)(bp + (long)8 * N);
    };
    auto store_tile = [&](int s, int buf) {
        float* Ah = sbuf + buf * STG + AH_OFF + ar * 17 + ac8;
        float* Al = sbuf + buf * STG + AL_OFF + ar * 17 + ac8;
        float h;
        float4 va0 = st[s][0], va1 = st[s][1];
        h = wmma::__float_to_tf32(va0.x); Ah[0] = h; Al[0] = wmma::__float_to_tf32(va0.x - h);
        h = wmma::__float_to_tf32(va0.y); Ah[1] = h; Al[1] = wmma::__float_to_tf32(va0.y - h);
        h = wmma::__float_to_tf32(va0.z); Ah[2] = h; Al[2] = wmma::__float_to_tf32(va0.z - h);
        h = wmma::__float_to_tf32(va0.w); Ah[3] = h; Al[3] = wmma::__float_to_tf32(va0.w - h);
        h = wmma::__float_to_tf32(va1.x); Ah[4] = h; Al[4] = wmma::__float_to_tf32(va1.x - h);
        h = wmma::__float_to_tf32(va1.y); Ah[5] = h; Al[5] = wmma::__float_to_tf32(va1.y - h);
        h = wmma::__float_to_tf32(va1.z); Ah[6] = h; Al[6] = wmma::__float_to_tf32(va1.z - h);
        h = wmma::__float_to_tf32(va1.w); Ah[7] = h; Al[7] = wmma::__float_to_tf32(va1.w - h);
        float* Bh = sbuf + buf * STG + BH_OFF + br * 68 + bc4;
        float* Bl = sbuf + buf * STG + BL_OFF + br * 68 + bc4;
        float4 vb0 = st[s][2], vb1 = st[s][3];
        h = wmma::__float_to_tf32(vb0.x); Bh[0] = h; Bl[0] = wmma::__float_to_tf32(vb0.x - h);
        h = wmma::__float_to_tf32(vb0.y); Bh[1] = h; Bl[1] = wmma::__float_to_tf32(vb0.y - h);
        h = wmma::__float_to_tf32(vb0.z); Bh[2] = h; Bl[2] = wmma::__float_to_tf32(vb0.z - h);
        h = wmma::__float_to_tf32(vb0.w); Bh[3] = h; Bl[3] = wmma::__float_to_tf32(vb0.w - h);
        Bh += 8 * 68; Bl += 8 * 68;
        h = wmma::__float_to_tf32(vb1.x); Bh[0] = h; Bl[0] = wmma::__float_to_tf32(vb1.x - h);
        h = wmma::__float_to_tf32(vb1.y); Bh[1] = h; Bl[1] = wmma::__float_to_tf32(vb1.y - h);
        h = wmma::__float_to_tf32(vb1.z); Bh[2] = h; Bl[2] = wmma::__float_to_tf32(vb1.z - h);
        h = wmma::__float_to_tf32(vb1.w); Bh[3] = h; Bl[3] = wmma::__float_to_tf32(vb1.w - h);
    };

    // prologue: tile0 -> set0, tile1 -> set1, convert tile0 -> buf0
    load_tile(0, 0);
    load_tile(16, 1);
    store_tile(0, 0);
    __syncthreads();

    for (int i = 0; i < nsteps; i++) {
        if (i + 2 < nsteps) load_tile((i + 2) << 4, i & 1);  // tile i+2 -> set (i&1)
        const float* Ah = sbuf + (i & 1) * STG + AH_OFF;
        const float* Al = sbuf + (i & 1) * STG + AL_OFF;
        const float* Bh = sbuf + (i & 1) * STG + BH_OFF;
        const float* Bl = sbuf + (i & 1) * STG + BL_OFF;
#pragma unroll
        for (int ks = 0; ks < 2; ks++) {
            wmma::fragment<wmma::matrix_a, 16, 16, 8, wmma::precision::tf32,
                           wmma::row_major> ah[2], al[2];
            wmma::fragment<wmma::matrix_b, 16, 16, 8, wmma::precision::tf32,
                           wmma::row_major> bh[2], bl[2];
#pragma unroll
            for (int x = 0; x < 2; x++) {
                wmma::load_matrix_sync(ah[x], Ah + (wr * 32 + x * 16) * 17 + ks * 8, 17);
                wmma::load_matrix_sync(al[x], Al + (wr * 32 + x * 16) * 17 + ks * 8, 17);
            }
#pragma unroll
            for (int y = 0; y < 2; y++) {
                wmma::load_matrix_sync(bh[y], Bh + (ks * 8) * 68 + wc * 32 + y * 16, 68);
                wmma::load_matrix_sync(bl[y], Bl + (ks * 8) * 68 + wc * 32 + y * 16, 68);
            }
#pragma unroll
            for (int x = 0; x < 2; x++)
#pragma unroll
                for (int y = 0; y < 2; y++) {
                    wmma::mma_sync(acc[x][y], al[x], bh[y], acc[x][y]);
                    wmma::mma_sync(acc[x][y], ah[x], bl[y], acc[x][y]);
                    wmma::mma_sync(acc[x][y], ah[x], bh[y], acc[x][y]);
                }
        }
        if (i + 1 < nsteps) store_tile((i + 1) & 1, (i + 1) & 1);  // convert tile i+1
        __syncthreads();
    }

    // epilogue: accumulators -> smem (reuse stage 0)
#pragma unroll
    for (int x = 0; x < 2; x++)
#pragma unroll
        for (int y = 0; y < 2; y++)
            wmma::store_matrix_sync(sbuf + (wr * 32 + x * 16) * 68 + wc * 32 + y * 16,
                                    acc[x][y], 68, wmma::mem_row_major);
    __syncthreads();

    if (act == 2) {
        // fused readout: silu then dot with w2, 16-lane reduce, atomicAdd
#pragma unroll
        for (int p = 0; p < 8; p++) {
            int idx = tid + p * 128;
            int r = idx >> 4;
            int c4 = (idx & 15) * 4;
            int gr = row0 + r;
            float part = 0.f;
            if (gr < M) {
#pragma unroll
                for (int j = 0; j < 4; j++) {
                    int gc = col0 + c4 + j;
                    float v = sbuf[r * 68 + c4 + j] + bias[gc];
                    v = v / (1.f + __expf(-v));
                    part += v * w2g[gc];
                }
            }
#pragma unroll
            for (int off = 8; off > 0; off >>= 1)
                part += __shfl_xor_sync(0xffffffffu, part, off, 16);
            if ((tid & 15) == 0 && gr < M) atomicAdd(&outp[gr], part);
        }
        return;
    }

#pragma unroll
    for (int p = 0; p < 8; p++) {
        int idx = tid + p * 128;
        int r = idx >> 4;
        int c4 = (idx & 15) * 4;
        int gr = row0 + r;
        if (gr >= M) continue;
        int gc = col0 + c4;
        float v0 = sbuf[r * 68 + c4 + 0] + bias[gc + 0];
        float v1 = sbuf[r * 68 + c4 + 1] + bias[gc + 1];
        float v2 = sbuf[r * 68 + c4 + 2] + bias[gc + 2];
        float v3 = sbuf[r * 68 + c4 + 3] + bias[gc + 3];
        if (act) {
            v0 = v0 / (1.f + __expf(-v0));
            v1 = v1 / (1.f + __expf(-v1));
            v2 = v2 / (1.f + __expf(-v2));
            v3 = v3 / (1.f + __expf(-v3));
        }
        float4 o = make_float4(v0, v1, v2, v3);
        *(float4*)(C + (long)gr * N + gc) = o;
    }
}

// ---------------- fused edge message + per-atom aggregation -------------------
__global__ void __launch_bounds__(128) msg_kernel(const float* __restrict__ Wf,
                                                  const float* __restrict__ bf,
                                                  int cur, int nxt) {
    int a = blockIdx.x;
    int f = blockIdx.y * 128 + threadIdx.x;

    float w0[NBF], w1[NBF], w2[NBF];
#pragma unroll
    for (int n = 0; n < NBF; n++) {
        w0[n] = Wf[n * F3 + f];
        w1[n] = Wf[n * F3 + FF + f];
        w2[n] = Wf[n * F3 + 2 * FF + f];
    }
    float b0 = bf[f], b1 = bf[FF + f], b2 = bf[2 * FF + f];

    float accs = 0.f, av0 = 0.f, av1 = 0.f, av2 = 0.f;
    int beg = g_offsets[a], end = g_offsets[a + 1];
    const float* __restrict__ nv_in = g_nv[cur];

    int s = (beg < end) ? g_ssend[beg] : 0;
    for (int i = beg; i < end; i++) {
        int snext = (i + 1 < end) ? g_ssend[i + 1] : 0;
        const float* __restrict__ so = g_so + (long)s * F3;
        float s0 = so[f], s1 = so[FF + f], s2 = so[2 * FF + f];
        const float* __restrict__ nvs = nv_in + (long)s * 3 * FF;
        float n0 = nvs[f], n1 = nvs[FF + f], n2 = nvs[2 * FF + f];
        const float* __restrict__ ed = g_sdat + (long)i * 24;
        float fcut = ed[0];
        float u0 = ed[1], u1 = ed[2], u2 = ed[3];
        float f0 = b0, f1 = b1, f2 = b2;
#pragma unroll
        for (int n = 0; n < NBF; n++) {
            float r = ed[4 + n];
            f0 += r * w0[n];
            f1 += r * w1[n];
            f2 += r * w2[n];
        }
        float gv = f0 * fcut * s0;
        float ge = f1 * fcut * s1;
        float ms = f2 * fcut * s2;
        av0 += n0 * gv + u0 * ge;
        av1 += n1 * gv + u1 * ge;
        av2 += n2 * gv + u2 * ge;
        accs += ms;
        s = snext;
    }
    g_ns[nxt][a * FF + f] = g_ns[cur][a * FF + f] + accs;
    float* nvo = g_nv[nxt] + (long)a * 3 * FF;
    const float* nvc = g_nv[cur] + (long)a * 3 * FF;
    nvo[f]          = nvc[f] + av0;
    nvo[FF + f]     = nvc[FF + f] + av1;
    nvo[2 * FF + f] = nvc[2 * FF + f] + av2;
}

// ---------------- update-phase elementwise kernels ----------------------------

__global__ void cat_kernel(int nxt) {
    int a = blockIdx.x;
    int f = threadIdx.x;
    const float* vv = g_Vv + (long)a * 3 * FF;
    float v0 = vv[f], v1 = vv[FF + f], v2 = vv[2 * FF + f];
    g_cat[a * 2 * FF + f] = sqrtf(v0 * v0 + v1 * v1 + v2 * v2);
    g_cat[a * 2 * FF + FF + f] = g_ns[nxt][a * FF + f];
}

__global__ void upd_kernel(int nxt) {
    int a = blockIdx.x;
    int f = threadIdx.x;
    const float* mo = g_so + (long)a * F3;
    float avv = mo[f], asv = mo[FF + f], ass = mo[2 * FF + f];
    const float* uv = g_Uv + (long)a * 3 * FF;
    const float* vv = g_Vv + (long)a * 3 * FF;
    float* nv = g_nv[nxt] + (long)a * 3 * FF;
    float dot = 0.f;
#pragma unroll
    for (int d = 0; d < 3; d++) {
        float u = uv[d * FF + f];
        dot += u * vv[d * FF + f];
        nv[d * FF + f] += avv * u;
    }
    g_ns[nxt][a * FF + f] += asv * dot + ass;
}

// ---------------- host driver -------------------------------------------------

static inline void launch_gemm(const float* A, const float* B, const float* bias,
                               float* C, int M, int K, int N, int act) {
    dim3 grid(N / 64, (M + 63) / 64, 1);
    tf32gemm_kernel<<<grid, 128>>>(A, B, bias, C, nullptr, nullptr, nullptr,
                                   M, K, N, act);
}

static inline void launch_gemm2(const float* A,
                                const float* B, const float* bias, float* C,
                                const float* B2, const float* bias2, float* C2,
                                int M, int K, int N, int act) {
    dim3 grid(N / 64, (M + 63) / 64, 2);
    tf32gemm_kernel<<<grid, 128>>>(A, B, bias, C, B2, bias2, C2, M, K, N, act);
}

static inline void launch_readout(const float* A, const float* B, const float* bias,
                                  const float* w2, float* out, int M, int K, int N) {
    dim3 grid(N / 64, (M + 63) / 64, 1);
    tf32gemm_kernel<<<grid, 128>>>(A, B, bias, nullptr, w2, nullptr, out,
                                   M, K, N, 2);
}

extern "C" void kernel_launch(void* const* d_in, const int* in_sizes, int n_in,
                              void* d_out, int out_size) {
    const int*   Z         = (const int*)d_in[0];
    const int*   edge      = (const int*)d_in[1];
    const float* edge_diff = (const float*)d_in[2];
    const float* edge_dist = (const float*)d_in[3];
    const float* embed     = (const float*)d_in[4];
    const float* msg_w_filter = (const float*)d_in[5];
    const float* msg_b_filter = (const float*)d_in[6];
    const float* msg_w1 = (const float*)d_in[7];
    const float* msg_b1 = (const float*)d_in[8];
    const float* msg_w2 = (const float*)d_in[9];
    const float* msg_b2 = (const float*)d_in[10];
    const float* upd_wU = (const float*)d_in[11];
    const float* upd_bU = (const float*)d_in[12];
    const float* upd_wV = (const float*)d_in[13];
    const float* upd_bV = (const float*)d_in[14];
    const float* upd_w1 = (const float*)d_in[15];
    const float* upd_b1 = (const float*)d_in[16];
    const float* upd_w2 = (const float*)d_in[17];
    const float* upd_b2 = (const float*)d_in[18];
    const float* ro_w1  = (const float*)d_in[19];
    const float* ro_b1  = (const float*)d_in[20];
    const float* ro_w2  = (const float*)d_in[21];
    const float* ro_b2  = (const float*)d_in[22];
    float* out = (float*)d_out;

    float *p_ns, *p_nv, *p_so, *p_hidden, *p_cat, *p_Uv, *p_Vv;
    cudaGetSymbolAddress((void**)&p_ns, g_ns);
    cudaGetSymbolAddress((void**)&p_nv, g_nv);
    cudaGetSymbolAddress((void**)&p_so, g_so);
    cudaGetSymbolAddress((void**)&p_hidden, g_hidden);
    cudaGetSymbolAddress((void**)&p_cat, g_cat);
    cudaGetSymbolAddress((void**)&p_Uv, g_Uv);
    cudaGetSymbolAddress((void**)&p_Vv, g_Vv);
    float* ns_buf[2] = {p_ns, p_ns + NA * FF};
    float* nv_buf[2] = {p_nv, p_nv + NA * 3 * FF};

    // prologue
    init_nodes_kernel<<<NA, FF>>>(Z, embed);
    zero_csr_kernel<<<(NA + 255) / 256, 256>>>(out, ro_b2);
    hist_kernel<<<(NE + 255) / 256, 256>>>(edge);

    // first layer's msg MLP (independent of CSR)
    launch_gemm(ns_buf[0], msg_w1, msg_b1, p_hidden, NA, FF, FF, 1);
    launch_gemm(p_hidden, msg_w2, msg_b2, p_so, NA, FF, F3, 0);

    // finish CSR
    scan_kernel<<<1, 1024>>>();
    prep_scatter_kernel<<<(NE + 255) / 256, 256>>>(edge, edge_diff, edge_dist);

    int cur = 0;
    for (int l = 0; l < LL; l++) {
        int nxt = 1 - cur;
        if (l > 0) {
            launch_gemm(ns_buf[cur], msg_w1 + (long)l * FF * FF, msg_b1 + l * FF,
                        p_hidden, NA, FF, FF, 1);
            launch_gemm(p_hidden, msg_w2 + (long)l * FF * F3, msg_b2 + l * F3,
                        p_so, NA, FF, F3, 0);
        }
        msg_kernel<<<dim3(NA, 2), 128>>>(msg_w_filter + (long)l * NBF * F3,
                                         msg_b_filter + l * F3, cur, nxt);
        launch_gemm2(nv_buf[nxt],
                     upd_wU + (long)l * FF * FF, upd_bU + l * FF, p_Uv,
                     upd_wV + (long)l * FF * FF, upd_bV + l * FF, p_Vv,
                     NA * 3, FF, FF, 0);
        cat_kernel<<<NA, FF>>>(nxt);
        launch_gemm(p_cat, upd_w1 + (long)l * 2 * FF * FF, upd_b1 + l * FF,
                    p_hidden, NA, 2 * FF, FF, 1);
        launch_gemm(p_hidden, upd_w2 + (long)l * FF * F3, upd_b2 + l * F3,
                    p_so, NA, FF, F3, 0);
        upd_kernel<<<NA, FF>>>(nxt);
        cur = nxt;
    }

    // fused readout (GEMM + silu + dot(w2) + atomicAdd), out preloaded with b2
    launch_readout(ns_buf[cur], ro_w1, ro_b1, ro_w2, out, NA, FF, FF);
}